// round 9
// baseline (speedup 1.0000x reference)
#include <cuda_runtime.h>
#include <cstdint>
#include <cstddef>

// ---------------------------------------------------------------------------
// 20 independent GEMMs (block-diagonal ensemble linear)
//   x:[32768,4000] f32, W:[2000,4000] f32, out:[32768,2000] f32
//   block n: out[:,n*100:+100] = x[:,n*200:+200] @ W[n*100:+100, n*200:+200]^T
//
// R9: HYBRID tensor + SIMT. Legacy HMMA tf32 on sm_100 is capped at ~200
// MAC/cyc/SM (measured invariant across R6/R7/R8). So: cols 0..63 of each
// block on HMMA (tf32), cols 64..99 on the fma pipe via fma.rn.f32x2
// (exact fp32), both issued from the same warps so the two pipes overlap.
// Persistent CTAs (20x7), W resident in SMEM, 3-slot cp.async ring for A.
// ---------------------------------------------------------------------------

static constexpr int NUM     = 20;
static constexpr int IN_SZ   = 200;
static constexpr int OUT_SZ  = 100;
static constexpr int X_LD    = 4000;
static constexpr int W_LD    = 4000;
static constexpr int OUT_LD  = 2000;

static constexpr int M_TILE  = 128;
static constexpr int KC      = 40;                // K chunk
static constexpr int KCH     = IN_SZ / KC;        // 5 chunks per M-tile
static constexpr int MT_PER_N   = 256;            // 32768/128
static constexpr int CTAS_PER_N = 7;

static constexpr int NSLOT   = 3;                 // A ring depth
static constexpr int STR_A   = 44;                // A row stride (floats): 12g+tg banks
static constexpr int STR_BT  = 204;               // tensor-B row stride
static constexpr int STR_TT  = 200;               // simt-B (k-contiguous) stride

static constexpr int A_ELEMS   = M_TILE * STR_A;  // 5632
static constexpr int BTL_ELEMS = 64 * STR_BT;     // 13056 (tensor W cols 0..63)
static constexpr int BTT_ELEMS = 36 * STR_TT;     // 7200  (simt  W cols 64..99)
static constexpr int OFF_BTT   = BTL_ELEMS;
static constexpr int OFF_A     = BTL_ELEMS + BTT_ELEMS;          // 20256
static constexpr int SMEM_FLOATS = OFF_A + NSLOT * A_ELEMS;      // 37152
static constexpr int SMEM_BYTES  = SMEM_FLOATS * 4;              // 148608

static constexpr int THREADS = 256;               // 8 warps: 4(wm) x 2(wn)

// ---------------------------------------------------------------------------
__device__ __forceinline__ uint32_t smem_u32(const void* p) {
    uint32_t a;
    asm("{ .reg .u64 t; cvta.to.shared.u64 t, %1; cvt.u32.u64 %0, t; }"
        : "=r"(a) : "l"(p));
    return a;
}
__device__ __forceinline__ void cp16(uint32_t dst, const float* src) {
    asm volatile("cp.async.cg.shared.global [%0], [%1], 16;"
                 :: "r"(dst), "l"(src));
}
#define CP_COMMIT() asm volatile("cp.async.commit_group;" ::: "memory")
#define CP_WAIT(n)  asm volatile("cp.async.wait_group %0;" :: "n"(n) : "memory")

__device__ __forceinline__ float f2tf32_rna(float f) {
    uint32_t r;
    asm("cvt.rna.tf32.f32 %0, %1;" : "=r"(r) : "f"(f));
    return __uint_as_float(r);
}

// tensor: D(16x8) += A(16x8 tf32) * B(8x8 tf32)
__device__ __forceinline__ void mma_tf32(float c[4],
                                         uint32_t a0, uint32_t a1, uint32_t a2, uint32_t a3,
                                         uint32_t b0, uint32_t b1) {
    asm volatile(
        "mma.sync.aligned.m16n8k8.row.col.f32.tf32.tf32.f32 "
        "{%0,%1,%2,%3}, {%4,%5,%6,%7}, {%8,%9}, {%0,%1,%2,%3};"
        : "+f"(c[0]), "+f"(c[1]), "+f"(c[2]), "+f"(c[3])
        : "r"(a0), "r"(a1), "r"(a2), "r"(a3), "r"(b0), "r"(b1));
}

// packed f32x2 helpers
__device__ __forceinline__ unsigned long long pack2(float lo, float hi) {
    unsigned long long r;
    asm("mov.b64 %0, {%1, %2};" : "=l"(r) : "f"(lo), "f"(hi));
    return r;
}
__device__ __forceinline__ void fma2(unsigned long long& acc,
                                     unsigned long long a, unsigned long long b) {
    asm("fma.rn.f32x2 %0, %1, %2, %0;" : "+l"(acc) : "l"(a), "l"(b));
}
__device__ __forceinline__ void unpack2(unsigned long long v, float& lo, float& hi) {
    asm("mov.b64 {%0, %1}, %2;" : "=f"(lo), "=f"(hi) : "l"(v));
}

// ---------------------------------------------------------------------------
// One CTA = ensemble block n, M-tiles {cta_m, cta_m+7, ...}
// ---------------------------------------------------------------------------
__global__ void __launch_bounds__(THREADS, 1)
ensemble_linear_hybrid_kernel(const float* __restrict__ x,
                              const float* __restrict__ W,
                              float* __restrict__ out) {
    extern __shared__ float smem[];
    float* Btl = smem;               // [64][204]  tensor W (tf32-rounded)
    float* Btt = smem + OFF_BTT;     // [36][200]  simt W (exact f32, k-contig)
    float* Arn = smem + OFF_A;       // [3][128*44] A ring
    const uint32_t a_base = smem_u32(Arn);

    const int tid = threadIdx.x;
    const int wid = tid >> 5;
    const int lid = tid & 31;
    const int g   = lid >> 2;    // 0..7  (rows for mma / x-rows for simt)
    const int tg  = lid & 3;     // 0..3  (k for mma / col-group j for simt)
    const int wm  = wid >> 1;    // 0..3  (M)
    const int wn  = wid & 1;     // 0..1  (N half)

    const int n     = blockIdx.x;      // 0..19
    const int cta_m = blockIdx.y;      // 0..6
    const int n_mt  = (MT_PER_N - cta_m + CTAS_PER_N - 1) / CTAS_PER_N;
    const int total_chunks = n_mt * KCH;

    // ---- one-time W staging ------------------------------------------------
    {
        const float* wbase = W + (size_t)n * OUT_SZ * W_LD + (size_t)n * IN_SZ;
        // tensor half: rows 0..63, RNA-rounded, stride 204
        for (int idx = tid; idx < 64 * 50; idx += THREADS) {
            int r  = idx / 50;
            int c4 = idx - r * 50;
            float4 v = *(const float4*)(wbase + (size_t)r * W_LD + c4 * 4);
            v.x = f2tf32_rna(v.x); v.y = f2tf32_rna(v.y);
            v.z = f2tf32_rna(v.z); v.w = f2tf32_rna(v.w);
            *(float4*)(Btl + r * STR_BT + c4 * 4) = v;
        }
        // simt half: rows 64..99 -> Btt[cc][k], exact f32, k contiguous
        for (int idx = tid; idx < 36 * 50; idx += THREADS) {
            int cc = idx / 50;
            int c4 = idx - cc * 50;
            float4 v = *(const float4*)(wbase + (size_t)(64 + cc) * W_LD + c4 * 4);
            *(float4*)(Btt + cc * STR_TT + c4 * 4) = v;
        }
    }

    const float* xbase = x + (size_t)n * IN_SZ;

    // ---- A chunk producer --------------------------------------------------
    auto produce = [&](int c) {
        if (c < total_chunks) {
            int ml = c / KCH;
            int kc = c - ml * KCH;
            int mt = cta_m + ml * CTAS_PER_N;
            const float* xs = xbase + (size_t)mt * M_TILE * X_LD + kc * KC;
            uint32_t dst = a_base + (uint32_t)((c % NSLOT) * A_ELEMS) * 4u;
            #pragma unroll
            for (int j = 0; j < 5; ++j) {
                int idx = tid + j * THREADS;
                int r = idx / 10;
                int i = idx - r * 10;
                cp16(dst + (uint32_t)(r * STR_A + i * 4) * 4u,
                     xs + (size_t)r * X_LD + i * 4);
            }
        }
        CP_COMMIT();
    };

    // accumulators
    float acc[2][4][4];                         // tensor: 2 m16 x 4 n8
    unsigned long long acc2[2][5];              // simt: row-pairs x up to 5 cols
    #pragma unroll
    for (int t = 0; t < 2; ++t)
        #pragma unroll
        for (int j = 0; j < 4; ++j)
            #pragma unroll
            for (int q = 0; q < 4; ++q) acc[t][j][q] = 0.0f;
    #pragma unroll
    for (int rp = 0; rp < 2; ++rp)
        #pragma unroll
        for (int c5 = 0; c5 < 5; ++c5) acc2[rp][c5] = 0ull;

    // simt column base within Btt: interleaved cols cc = base + tg + 4*c'
    const int cc_base = wn ? 20 : 0;   // wn0: cols 64..83 (5/lane), wn1: 84..99 (4/lane)

    produce(0);
    produce(1);

    // ---- mainloop ----------------------------------------------------------
    for (int c = 0; c < total_chunks; ++c) {
        CP_WAIT(1);
        __syncthreads();

        produce(c + 2);

        const float* Ab = Arn + (c % NSLOT) * A_ELEMS;
        const int kc = c % KCH;
        const int kg = kc * KC;

        // ===== tensor part: cols 0..63, tf32 HMMA (fire-and-forget) =========
        #pragma unroll
        for (int ks = 0; ks < KC / 8; ++ks) {
            const int k0 = ks * 8;
            uint32_t a[2][4];
            #pragma unroll
            for (int t = 0; t < 2; ++t) {
                const uint32_t* ap = (const uint32_t*)(Ab + (wm * 32 + t * 16 + g) * STR_A + k0 + tg);
                a[t][0] = ap[0];
                a[t][1] = ap[8 * STR_A];
                a[t][2] = ap[4];
                a[t][3] = ap[8 * STR_A + 4];
            }
            uint32_t b[4][2];
            #pragma unroll
            for (int j = 0; j < 4; ++j) {
                const uint32_t* bp = (const uint32_t*)(Btl + (wn * 32 + j * 8 + g) * STR_BT + kg + k0 + tg);
                b[j][0] = bp[0];
                b[j][1] = bp[4];
            }
            #pragma unroll
            for (int t = 0; t < 2; ++t)
                #pragma unroll
                for (int j = 0; j < 4; ++j)
                    mma_tf32(acc[t][j], a[t][0], a[t][1], a[t][2], a[t][3],
                             b[j][0], b[j][1]);
        }

        // ===== simt part: cols 64..99, exact fp32 via fma.rn.f32x2 ==========
        // lane g = x-row group (rows g+8r'), lane tg = column group j.
        #pragma unroll 2
        for (int t4 = 0; t4 < KC / 4; ++t4) {
            const int kl = t4 * 4;                 // local k in chunk
            float4 xa[4];
            #pragma unroll
            for (int rp4 = 0; rp4 < 4; ++rp4)
                xa[rp4] = *(const float4*)(Ab + (wm * 32 + g + 8 * rp4) * STR_A + kl);
            float4 wb[5];
            #pragma unroll
            for (int c5 = 0; c5 < 4; ++c5)
                wb[c5] = *(const float4*)(Btt + (cc_base + tg + 4 * c5) * STR_TT + kg + kl);
            if (wn == 0)
                wb[4] = *(const float4*)(Btt + (cc_base + tg + 16) * STR_TT + kg + kl);

            #pragma unroll
            for (int q = 0; q < 4; ++q) {
                const float* xq0 = (const float*)&xa[0];
                const float* xq1 = (const float*)&xa[1];
                const float* xq2 = (const float*)&xa[2];
                const float* xq3 = (const float*)&xa[3];
                unsigned long long xp0 = pack2(xq0[q], xq1[q]);  // rows g, g+8
                unsigned long long xp1 = pack2(xq2[q], xq3[q]);  // rows g+16, g+24
                #pragma unroll
                for (int c5 = 0; c5 < 4; ++c5) {
                    const float* wq = (const float*)&wb[c5];
                    unsigned long long wd = pack2(wq[q], wq[q]);
                    fma2(acc2[0][c5], xp0, wd);
                    fma2(acc2[1][c5], xp1, wd);
                }
                if (wn == 0) {
                    const float* wq = (const float*)&wb[4];
                    unsigned long long wd = pack2(wq[q], wq[q]);
                    fma2(acc2[0][4], xp0, wd);
                    fma2(acc2[1][4], xp1, wd);
                }
            }
        }

        // ===== per-M-tile epilogue ==========================================
        if (kc == KCH - 1) {
            const int mt = cta_m + (c / KCH) * CTAS_PER_N;
            // tensor cols 0..63
            #pragma unroll
            for (int t = 0; t < 2; ++t) {
                const int r0 = mt * M_TILE + wm * 32 + t * 16 + g;
                float* orow = out + (size_t)r0 * OUT_LD + (size_t)n * OUT_SZ;
                #pragma unroll
                for (int j = 0; j < 4; ++j) {
                    const int cgl = wn * 32 + j * 8 + 2 * tg;   // 0..62
                    *(float2*)(orow + cgl) =
                        make_float2(acc[t][j][0], acc[t][j][1]);
                    *(float2*)(orow + (size_t)8 * OUT_LD + cgl) =
                        make_float2(acc[t][j][2], acc[t][j][3]);
                    #pragma unroll
                    for (int q = 0; q < 4; ++q) acc[t][j][q] = 0.0f;
                }
            }
            // simt cols 64..99
            #pragma unroll
            for (int rp = 0; rp < 2; ++rp) {
                #pragma unroll
                for (int c5 = 0; c5 < 5; ++c5) {
                    if (c5 == 4 && wn != 0) continue;
                    float lo, hi;
                    unpack2(acc2[rp][c5], lo, hi);
                    const int gcol = 64 + cc_base + tg + 4 * c5;
                    const int rlo = mt * M_TILE + wm * 32 + g + 8 * (2 * rp);
                    const int rhi = rlo + 8;
                    out[(size_t)rlo * OUT_LD + (size_t)n * OUT_SZ + gcol] = lo;
                    out[(size_t)rhi * OUT_LD + (size_t)n * OUT_SZ + gcol] = hi;
                    acc2[rp][c5] = 0ull;
                }
            }
        }
    }
}

// ---------------------------------------------------------------------------
extern "C" void kernel_launch(void* const* d_in, const int* in_sizes, int n_in,
                              void* d_out, int out_size) {
    const float* x = (const float*)d_in[0];   // [32768, 4000]
    const float* W = (const float*)d_in[1];   // [2000, 4000]
    float* out = (float*)d_out;               // [32768, 2000]

    cudaFuncSetAttribute(ensemble_linear_hybrid_kernel,
                         cudaFuncAttributeMaxDynamicSharedMemorySize,
                         SMEM_BYTES);

    dim3 grid(NUM, CTAS_PER_N, 1);            // 20 x 7 = 140 CTAs
    ensemble_linear_hybrid_kernel<<<grid, THREADS, SMEM_BYTES>>>(x, W, out);
}

// round 10
// speedup vs baseline: 2.4641x; 2.4641x over previous
#include <cuda_runtime.h>
#include <cuda_fp16.h>
#include <cstdint>
#include <cstddef>

// ---------------------------------------------------------------------------
// 20 independent GEMMs (block-diagonal ensemble linear)
//   x:[32768,4000] f32, W:[2000,4000] f32, out:[32768,2000] f32
//   block n: out[:,n*100:+100] = x[:,n*200:+200] @ W[n*100:+100, n*200:+200]^T
//
// R10: fp16 HMMA (m16n8k16, fp32 accumulate). Theory: legacy-HMMA on sm_100
// is instruction-rate capped (~1 HMMA / 20cyc / SMSP measured with
// m16n8k8.tf32 = 200 MAC/cyc/SM); m16n8k16.f16 carries 2x MACs/instr.
// fp16 mantissa (10 bits) == tf32 mantissa; products exact, accum fp32.
// Persistent CTAs (20x7). W resident in SMEM as fp16. A kept f32 in a
// 4-slot cp.async ring; converted to f16x2 at fragment load.
// K=200 = 4 chunks of 48 (3 k16 steps each) + one 8-wide tail (m16n8k8.f16).
// ---------------------------------------------------------------------------

static constexpr int NUM     = 20;
static constexpr int IN_SZ   = 200;
static constexpr int OUT_SZ  = 100;
static constexpr int X_LD    = 4000;
static constexpr int W_LD    = 4000;
static constexpr int OUT_LD  = 2000;

static constexpr int M_TILE  = 128;
static constexpr int KCH     = 5;                 // 4x48 + 1x8
static constexpr int MT_PER_N   = 256;            // 32768/128
static constexpr int CTAS_PER_N = 7;

static constexpr int NSLOT   = 4;                 // A ring depth
static constexpr int STR_A   = 52;                // A slot row stride (f32); banks 20g+2tg distinct
static constexpr int STR_BH  = 216;               // B row stride (halves); banks 12g distinct

static constexpr int A_ELEMS   = M_TILE * STR_A;          // 6656 f32 / slot
static constexpr int B_BYTES   = 112 * STR_BH * 2;        // 48384
static constexpr int A_BYTES   = NSLOT * A_ELEMS * 4;     // 106496
static constexpr int SMEM_BYTES = B_BYTES + A_BYTES;      // 154880

static constexpr int THREADS = 256;               // 8 warps: 4(wm) x 2(wn)
// warp tile 32(M) x 56(N): 2 m16 x 7 n8

// ---------------------------------------------------------------------------
__device__ __forceinline__ uint32_t smem_u32(const void* p) {
    uint32_t a;
    asm("{ .reg .u64 t; cvta.to.shared.u64 t, %1; cvt.u32.u64 %0, t; }"
        : "=r"(a) : "l"(p));
    return a;
}
__device__ __forceinline__ void cp16(uint32_t dst, const float* src) {
    asm volatile("cp.async.cg.shared.global [%0], [%1], 16;"
                 :: "r"(dst), "l"(src));
}
#define CP_COMMIT() asm volatile("cp.async.commit_group;" ::: "memory")
#define CP_WAIT(n)  asm volatile("cp.async.wait_group %0;" :: "n"(n) : "memory")

// pack two f32 -> f16x2 reg; lo half = first (lower-k) element
__device__ __forceinline__ uint32_t cvt_f16x2(float lo, float hi) {
    uint32_t r;
    asm("cvt.rn.f16x2.f32 %0, %1, %2;" : "=r"(r) : "f"(hi), "f"(lo));
    return r;
}

// D(16x8,f32) += A(16x16,f16) * B(16x8,f16)  [row.col]
__device__ __forceinline__ void mma_f16_k16(float c[4],
                                            uint32_t a0, uint32_t a1, uint32_t a2, uint32_t a3,
                                            uint32_t b0, uint32_t b1) {
    asm volatile(
        "mma.sync.aligned.m16n8k16.row.col.f32.f16.f16.f32 "
        "{%0,%1,%2,%3}, {%4,%5,%6,%7}, {%8,%9}, {%0,%1,%2,%3};"
        : "+f"(c[0]), "+f"(c[1]), "+f"(c[2]), "+f"(c[3])
        : "r"(a0), "r"(a1), "r"(a2), "r"(a3), "r"(b0), "r"(b1));
}
// D(16x8,f32) += A(16x8,f16) * B(8x8,f16)  [row.col]
__device__ __forceinline__ void mma_f16_k8(float c[4],
                                           uint32_t a0, uint32_t a1, uint32_t b0) {
    asm volatile(
        "mma.sync.aligned.m16n8k8.row.col.f32.f16.f16.f32 "
        "{%0,%1,%2,%3}, {%4,%5}, {%6}, {%0,%1,%2,%3};"
        : "+f"(c[0]), "+f"(c[1]), "+f"(c[2]), "+f"(c[3])
        : "r"(a0), "r"(a1), "r"(b0));
}

// ---------------------------------------------------------------------------
// One CTA = ensemble block n, M-tiles {cta_m, cta_m+7, ...}
// ---------------------------------------------------------------------------
__global__ void __launch_bounds__(THREADS, 1)
ensemble_linear_f16_kernel(const float* __restrict__ x,
                           const float* __restrict__ W,
                           float* __restrict__ out) {
    extern __shared__ char smem[];
    __half* Bh  = (__half*)smem;                 // [112][216] fp16, resident
    float*  Arn = (float*)(smem + B_BYTES);      // [4][128*52] f32 ring
    const uint32_t a_base = smem_u32(Arn);

    const int tid = threadIdx.x;
    const int wid = tid >> 5;
    const int lid = tid & 31;
    const int g   = lid >> 2;    // 0..7
    const int tg  = lid & 3;     // 0..3
    const int wm  = wid >> 1;    // 0..3 (M)
    const int wn  = wid & 1;     // 0..1 (N)

    const int n     = blockIdx.x;      // 0..19
    const int cta_m = blockIdx.y;      // 0..6
    const int n_mt  = (MT_PER_N - cta_m + CTAS_PER_N - 1) / CTAS_PER_N;
    const int total_chunks = n_mt * KCH;

    // ---- one-time W staging: f32 -> fp16, rows 0..99 + zero pad 100..111 ---
    {
        const float* wbase = W + (size_t)n * OUT_SZ * W_LD + (size_t)n * IN_SZ;
        for (int idx = tid; idx < OUT_SZ * 50; idx += THREADS) {
            int r  = idx / 50;
            int c4 = idx - r * 50;
            float4 v = *(const float4*)(wbase + (size_t)r * W_LD + c4 * 4);
            uint2 u;
            u.x = cvt_f16x2(v.x, v.y);
            u.y = cvt_f16x2(v.z, v.w);
            *(uint2*)(Bh + r * STR_BH + c4 * 4) = u;   // 8B aligned (432B rows)
        }
        for (int i = tid; i < 12 * STR_BH; i += THREADS) {
            int r = 100 + i / STR_BH;
            int c = i - (i / STR_BH) * STR_BH;
            Bh[r * STR_BH + c] = __float2half(0.0f);
        }
    }

    const float* xbase = x + (size_t)n * IN_SZ;

    // ---- A chunk producer (cp.async). Chunk kc<4: 48 cols; kc==4: 8 cols ---
    auto produce = [&](int c) {
        if (c < total_chunks) {
            int ml = c / KCH;
            int kc = c - ml * KCH;
            int mt = cta_m + ml * CTAS_PER_N;
            const float* xs = xbase + (size_t)mt * M_TILE * X_LD + kc * 48;
            uint32_t dst = a_base + (uint32_t)((c % NSLOT) * A_ELEMS) * 4u;
            if (kc < 4) {
                // 128 rows x 12 float4 = 1536 ops -> 6/thread
                #pragma unroll
                for (int j = 0; j < 6; ++j) {
                    int idx = tid + j * THREADS;
                    int r = idx / 12;
                    int i = idx - r * 12;
                    cp16(dst + (uint32_t)(r * STR_A + i * 4) * 4u,
                         xs + (size_t)r * X_LD + i * 4);
                }
            } else {
                // tail: 128 rows x 2 float4 = 256 ops -> 1/thread
                int r = tid >> 1;
                int i = tid & 1;
                cp16(dst + (uint32_t)(r * STR_A + i * 4) * 4u,
                     xs + (size_t)r * X_LD + i * 4);
            }
        }
        CP_COMMIT();
    };

    float acc[2][7][4];
    #pragma unroll
    for (int t = 0; t < 2; ++t)
        #pragma unroll
        for (int j = 0; j < 7; ++j)
            #pragma unroll
            for (int q = 0; q < 4; ++q) acc[t][j][q] = 0.0f;

    produce(0);
    produce(1);
    produce(2);

    // ---- mainloop ----------------------------------------------------------
    for (int c = 0; c < total_chunks; ++c) {
        CP_WAIT(2);            // chunk c resident
        __syncthreads();       // visible to all; also: chunk c-1 fully consumed

        produce(c + 3);        // refills slot (c-1)%4 — safe after the sync

        const float* Ab = Arn + (c % NSLOT) * A_ELEMS;
        const int kc = c % KCH;
        const int kg = kc * 48;          // k base within the block's K=200

        if (kc < 4) {
            #pragma unroll
            for (int ks = 0; ks < 3; ++ks) {      // 3 k16 steps
                const int k0 = ks * 16;
                uint32_t a[2][4];
                #pragma unroll
                for (int t = 0; t < 2; ++t) {
                    const int row = wm * 32 + t * 16 + g;
                    const float* base = Ab + row * STR_A + k0 + 2 * tg;
                    float2 v00 = *(const float2*)(base);
                    float2 v10 = *(const float2*)(base + 8 * STR_A);
                    float2 v01 = *(const float2*)(base + 8);
                    float2 v11 = *(const float2*)(base + 8 * STR_A + 8);
                    a[t][0] = cvt_f16x2(v00.x, v00.y);
                    a[t][1] = cvt_f16x2(v10.x, v10.y);
                    a[t][2] = cvt_f16x2(v01.x, v01.y);
                    a[t][3] = cvt_f16x2(v11.x, v11.y);
                }
                uint32_t b[7][2];
                #pragma unroll
                for (int j = 0; j < 7; ++j) {
                    const int col = wn * 56 + j * 8 + g;
                    const uint32_t* bp =
                        (const uint32_t*)(Bh + col * STR_BH + kg + k0 + 2 * tg);
                    b[j][0] = bp[0];
                    b[j][1] = bp[4];   // +8 halves = +16B
                }
                #pragma unroll
                for (int t = 0; t < 2; ++t)
                    #pragma unroll
                    for (int j = 0; j < 7; ++j)
                        mma_f16_k16(acc[t][j], a[t][0], a[t][1], a[t][2], a[t][3],
                                    b[j][0], b[j][1]);
            }
        } else {
            // tail: one k8 step (k = 192..199)
            uint32_t a[2][2];
            #pragma unroll
            for (int t = 0; t < 2; ++t) {
                const int row = wm * 32 + t * 16 + g;
                const float* base = Ab + row * STR_A + 2 * tg;
                float2 v0 = *(const float2*)(base);
                float2 v1 = *(const float2*)(base + 8 * STR_A);
                a[t][0] = cvt_f16x2(v0.x, v0.y);
                a[t][1] = cvt_f16x2(v1.x, v1.y);
            }
            uint32_t b[7];
            #pragma unroll
            for (int j = 0; j < 7; ++j) {
                const int col = wn * 56 + j * 8 + g;
                b[j] = *(const uint32_t*)(Bh + col * STR_BH + kg + 2 * tg);
            }
            #pragma unroll
            for (int t = 0; t < 2; ++t)
                #pragma unroll
                for (int j = 0; j < 7; ++j)
                    mma_f16_k8(acc[t][j], a[t][0], a[t][1], b[j]);
        }

        // ---- per-M-tile epilogue after last k-chunk ------------------------
        if (kc == KCH - 1) {
            const int mt = cta_m + (c / KCH) * CTAS_PER_N;
            const int row_base = mt * M_TILE + wm * 32;
            #pragma unroll
            for (int t = 0; t < 2; ++t) {
                const int r0 = row_base + t * 16 + g;
                float* orow = out + (size_t)r0 * OUT_LD + (size_t)n * OUT_SZ;
                #pragma unroll
                for (int j = 0; j < 7; ++j) {
                    const int cgl = wn * 56 + j * 8 + 2 * tg;   // even, 0..110
                    if (cgl < OUT_SZ) {
                        *(float2*)(orow + cgl) =
                            make_float2(acc[t][j][0], acc[t][j][1]);
                        *(float2*)(orow + (size_t)8 * OUT_LD + cgl) =
                            make_float2(acc[t][j][2], acc[t][j][3]);
                    }
                    #pragma unroll
                    for (int q = 0; q < 4; ++q) acc[t][j][q] = 0.0f;
                }
            }
        }
    }
}

// ---------------------------------------------------------------------------
extern "C" void kernel_launch(void* const* d_in, const int* in_sizes, int n_in,
                              void* d_out, int out_size) {
    const float* x = (const float*)d_in[0];   // [32768, 4000]
    const float* W = (const float*)d_in[1];   // [2000, 4000]
    float* out = (float*)d_out;               // [32768, 2000]

    cudaFuncSetAttribute(ensemble_linear_f16_kernel,
                         cudaFuncAttributeMaxDynamicSharedMemorySize,
                         SMEM_BYTES);

    dim3 grid(NUM, CTAS_PER_N, 1);            // 20 x 7 = 140 CTAs
    ensemble_linear_f16_kernel<<<grid, THREADS, SMEM_BYTES>>>(x, W, out);
}

// round 12
// speedup vs baseline: 2.5805x; 1.0472x over previous
#include <cuda_runtime.h>
#include <cuda_fp16.h>
#include <cstdint>
#include <cstddef>

// ---------------------------------------------------------------------------
// 20 independent GEMMs (block-diagonal ensemble linear)
//   x:[32768,4000] f32, W:[2000,4000] f32, out:[32768,2000] f32
//   block n: out[:,n*100:+100] = x[:,n*200:+200] @ W[n*100:+100, n*200:+200]^T
//
// R12 (= R11 re-bench; previous round died on infra, not the kernel):
// fp16 HMMA (m16n8k16, fp32 accum) + 512-thread persistent CTAs.
// R10 showed all pipes idle at 268us (tensor 20%, DRAM 35%, issue 17%) ->
// latency-bound with 8 warps/SM. This round: 16 warps/SM, M_TILE=256,
// 49KB A-chunks in a 3-slot cp.async ring (~98KB in flight per SM),
// W resident in SMEM as fp16 (48KB). Same per-warp 32x56 fp16 tile.
// ---------------------------------------------------------------------------

static constexpr int NUM     = 20;
static constexpr int IN_SZ   = 200;
static constexpr int OUT_SZ  = 100;
static constexpr int X_LD    = 4000;
static constexpr int W_LD    = 4000;
static constexpr int OUT_LD  = 2000;

static constexpr int M_TILE  = 256;
static constexpr int KCH     = 5;                 // 4x48 + 1x8
static constexpr int MT_PER_N   = 128;            // 32768/256
static constexpr int CTAS_PER_N = 7;

static constexpr int NSLOT   = 3;                 // A ring depth
static constexpr int STR_A   = 52;                // A slot row stride (f32)
static constexpr int STR_BH  = 216;               // B row stride (halves)

static constexpr int A_ELEMS   = M_TILE * STR_A;          // 13312 f32 / slot
static constexpr int B_BYTES   = 112 * STR_BH * 2;        // 48384
static constexpr int A_BYTES   = NSLOT * A_ELEMS * 4;     // 159744
static constexpr int SMEM_BYTES = B_BYTES + A_BYTES;      // 208128

static constexpr int THREADS = 512;               // 16 warps: 8(wm) x 2(wn)
// warp tile 32(M) x 56(N): 2 m16 x 7 n8

// ---------------------------------------------------------------------------
__device__ __forceinline__ uint32_t smem_u32(const void* p) {
    uint32_t a;
    asm("{ .reg .u64 t; cvta.to.shared.u64 t, %1; cvt.u32.u64 %0, t; }"
        : "=r"(a) : "l"(p));
    return a;
}
__device__ __forceinline__ void cp16(uint32_t dst, const float* src) {
    asm volatile("cp.async.cg.shared.global [%0], [%1], 16;"
                 :: "r"(dst), "l"(src));
}
#define CP_COMMIT() asm volatile("cp.async.commit_group;" ::: "memory")
#define CP_WAIT(n)  asm volatile("cp.async.wait_group %0;" :: "n"(n) : "memory")

// pack two f32 -> f16x2 reg; lo half = first (lower-k) element
__device__ __forceinline__ uint32_t cvt_f16x2(float lo, float hi) {
    uint32_t r;
    asm("cvt.rn.f16x2.f32 %0, %1, %2;" : "=r"(r) : "f"(hi), "f"(lo));
    return r;
}

// D(16x8,f32) += A(16x16,f16) * B(16x8,f16)  [row.col]
__device__ __forceinline__ void mma_f16_k16(float c[4],
                                            uint32_t a0, uint32_t a1, uint32_t a2, uint32_t a3,
                                            uint32_t b0, uint32_t b1) {
    asm volatile(
        "mma.sync.aligned.m16n8k16.row.col.f32.f16.f16.f32 "
        "{%0,%1,%2,%3}, {%4,%5,%6,%7}, {%8,%9}, {%0,%1,%2,%3};"
        : "+f"(c[0]), "+f"(c[1]), "+f"(c[2]), "+f"(c[3])
        : "r"(a0), "r"(a1), "r"(a2), "r"(a3), "r"(b0), "r"(b1));
}
// D(16x8,f32) += A(16x8,f16) * B(8x8,f16)  [row.col]
__device__ __forceinline__ void mma_f16_k8(float c[4],
                                           uint32_t a0, uint32_t a1, uint32_t b0) {
    asm volatile(
        "mma.sync.aligned.m16n8k8.row.col.f32.f16.f16.f32 "
        "{%0,%1,%2,%3}, {%4,%5}, {%6}, {%0,%1,%2,%3};"
        : "+f"(c[0]), "+f"(c[1]), "+f"(c[2]), "+f"(c[3])
        : "r"(a0), "r"(a1), "r"(b0));
}

// ---------------------------------------------------------------------------
// One CTA = ensemble block n, M-tiles {cta_m, cta_m+7, ...} (M_TILE=256)
// ---------------------------------------------------------------------------
__global__ void __launch_bounds__(THREADS, 1)
ensemble_linear_f16x2w_kernel(const float* __restrict__ x,
                              const float* __restrict__ W,
                              float* __restrict__ out) {
    extern __shared__ char smem[];
    __half* Bh  = (__half*)smem;                 // [112][216] fp16, resident
    float*  Arn = (float*)(smem + B_BYTES);      // [3][256*52] f32 ring
    const uint32_t a_base = smem_u32(Arn);

    const int tid = threadIdx.x;
    const int wid = tid >> 5;
    const int lid = tid & 31;
    const int g   = lid >> 2;    // 0..7
    const int tg  = lid & 3;     // 0..3
    const int wm  = wid >> 1;    // 0..7 (M)
    const int wn  = wid & 1;     // 0..1 (N)

    const int n     = blockIdx.x;      // 0..19
    const int cta_m = blockIdx.y;      // 0..6
    const int n_mt  = (MT_PER_N - cta_m + CTAS_PER_N - 1) / CTAS_PER_N;
    const int total_chunks = n_mt * KCH;

    // ---- one-time W staging: f32 -> fp16, rows 0..99 + zero pad 100..111 ---
    {
        const float* wbase = W + (size_t)n * OUT_SZ * W_LD + (size_t)n * IN_SZ;
        for (int idx = tid; idx < OUT_SZ * 50; idx += THREADS) {
            int r  = idx / 50;
            int c4 = idx - r * 50;
            float4 v = *(const float4*)(wbase + (size_t)r * W_LD + c4 * 4);
            uint2 u;
            u.x = cvt_f16x2(v.x, v.y);
            u.y = cvt_f16x2(v.z, v.w);
            *(uint2*)(Bh + r * STR_BH + c4 * 4) = u;
        }
        for (int i = tid; i < 12 * STR_BH; i += THREADS) {
            int r = 100 + i / STR_BH;
            int c = i - (i / STR_BH) * STR_BH;
            Bh[r * STR_BH + c] = __float2half(0.0f);
        }
    }

    const float* xbase = x + (size_t)n * IN_SZ;

    // ---- A chunk producer (cp.async). kc<4: 48 cols; kc==4: 8 cols ---------
    auto produce = [&](int c) {
        if (c < total_chunks) {
            int ml = c / KCH;
            int kc = c - ml * KCH;
            int mt = cta_m + ml * CTAS_PER_N;
            const float* xs = xbase + (size_t)mt * M_TILE * X_LD + kc * 48;
            uint32_t dst = a_base + (uint32_t)((c % NSLOT) * A_ELEMS) * 4u;
            if (kc < 4) {
                // 256 rows x 12 float4 = 3072 ops -> 6/thread
                #pragma unroll
                for (int j = 0; j < 6; ++j) {
                    int idx = tid + j * THREADS;
                    int r = idx / 12;
                    int i = idx - r * 12;
                    cp16(dst + (uint32_t)(r * STR_A + i * 4) * 4u,
                         xs + (size_t)r * X_LD + i * 4);
                }
            } else {
                // tail: 256 rows x 2 float4 = 512 ops -> 1/thread
                int r = tid >> 1;
                int i = tid & 1;
                cp16(dst + (uint32_t)(r * STR_A + i * 4) * 4u,
                     xs + (size_t)r * X_LD + i * 4);
            }
        }
        CP_COMMIT();
    };

    float acc[2][7][4];
    #pragma unroll
    for (int t = 0; t < 2; ++t)
        #pragma unroll
        for (int j = 0; j < 7; ++j)
            #pragma unroll
            for (int q = 0; q < 4; ++q) acc[t][j][q] = 0.0f;

    produce(0);
    produce(1);

    // ---- mainloop ----------------------------------------------------------
    for (int c = 0; c < total_chunks; ++c) {
        CP_WAIT(1);            // chunk c resident
        __syncthreads();       // visible to all; chunk c-1 fully consumed

        produce(c + 2);        // refills slot (c-1)%3 — safe after the sync

        const float* Ab = Arn + (c % NSLOT) * A_ELEMS;
        const int kc = c % KCH;
        const int kg = kc * 48;          // k base within the block's K=200

        if (kc < 4) {
            #pragma unroll
            for (int ks = 0; ks < 3; ++ks) {      // 3 k16 steps
                const int k0 = ks * 16;
                uint32_t a[2][4];
                #pragma unroll
                for (int t = 0; t < 2; ++t) {
                    const int row = wm * 32 + t * 16 + g;
                    const float* base = Ab + row * STR_A + k0 + 2 * tg;
                    float2 v00 = *(const float2*)(base);
                    float2 v10 = *(const float2*)(base + 8 * STR_A);
                    float2 v01 = *(const float2*)(base + 8);
                    float2 v11 = *(const float2*)(base + 8 * STR_A + 8);
                    a[t][0] = cvt_f16x2(v00.x, v00.y);
                    a[t][1] = cvt_f16x2(v10.x, v10.y);
                    a[t][2] = cvt_f16x2(v01.x, v01.y);
                    a[t][3] = cvt_f16x2(v11.x, v11.y);
                }
                uint32_t b[7][2];
                #pragma unroll
                for (int j = 0; j < 7; ++j) {
                    const int col = wn * 56 + j * 8 + g;
                    const uint32_t* bp =
                        (const uint32_t*)(Bh + col * STR_BH + kg + k0 + 2 * tg);
                    b[j][0] = bp[0];
                    b[j][1] = bp[4];   // +8 halves = +16B
                }
                #pragma unroll
                for (int t = 0; t < 2; ++t)
                    #pragma unroll
                    for (int j = 0; j < 7; ++j)
                        mma_f16_k16(acc[t][j], a[t][0], a[t][1], a[t][2], a[t][3],
                                    b[j][0], b[j][1]);
            }
        } else {
            // tail: one k8 step (k = 192..199)
            uint32_t a[2][2];
            #pragma unroll
            for (int t = 0; t < 2; ++t) {
                const int row = wm * 32 + t * 16 + g;
                const float* base = Ab + row * STR_A + 2 * tg;
                float2 v0 = *(const float2*)(base);
                float2 v1 = *(const float2*)(base + 8 * STR_A);
                a[t][0] = cvt_f16x2(v0.x, v0.y);
                a[t][1] = cvt_f16x2(v1.x, v1.y);
            }
            uint32_t b[7];
            #pragma unroll
            for (int j = 0; j < 7; ++j) {
                const int col = wn * 56 + j * 8 + g;
                b[j] = *(const uint32_t*)(Bh + col * STR_BH + kg + 2 * tg);
            }
            #pragma unroll
            for (int t = 0; t < 2; ++t)
                #pragma unroll
                for (int j = 0; j < 7; ++j)
                    mma_f16_k8(acc[t][j], a[t][0], a[t][1], b[j]);
        }

        // ---- per-M-tile epilogue after last k-chunk ------------------------
        if (kc == KCH - 1) {
            const int mt = cta_m + (c / KCH) * CTAS_PER_N;
            const int row_base = mt * M_TILE + wm * 32;
            #pragma unroll
            for (int t = 0; t < 2; ++t) {
                const int r0 = row_base + t * 16 + g;
                float* orow = out + (size_t)r0 * OUT_LD + (size_t)n * OUT_SZ;
                #pragma unroll
                for (int j = 0; j < 7; ++j) {
                    const int cgl = wn * 56 + j * 8 + 2 * tg;   // even, 0..110
                    if (cgl < OUT_SZ) {
                        *(float2*)(orow + cgl) =
                            make_float2(acc[t][j][0], acc[t][j][1]);
                        *(float2*)(orow + (size_t)8 * OUT_LD + cgl) =
                            make_float2(acc[t][j][2], acc[t][j][3]);
                    }
                    #pragma unroll
                    for (int q = 0; q < 4; ++q) acc[t][j][q] = 0.0f;
                }
            }
        }
    }
}

// ---------------------------------------------------------------------------
extern "C" void kernel_launch(void* const* d_in, const int* in_sizes, int n_in,
                              void* d_out, int out_size) {
    const float* x = (const float*)d_in[0];   // [32768, 4000]
    const float* W = (const float*)d_in[1];   // [2000, 4000]
    float* out = (float*)d_out;               // [32768, 2000]

    static bool attr_set = false;
    if (!attr_set) {
        cudaFuncSetAttribute(ensemble_linear_f16x2w_kernel,
                             cudaFuncAttributeMaxDynamicSharedMemorySize,
                             SMEM_BYTES);
        attr_set = true;
    }

    dim3 grid(NUM, CTAS_PER_N, 1);            // 20 x 7 = 140 CTAs
    ensemble_linear_f16x2w_kernel<<<grid, THREADS, SMEM_BYTES>>>(x, W, out);
}